// round 6
// baseline (speedup 1.0000x reference)
#include <cuda_runtime.h>

// ReduceBoundingBoxes, SINGLE kernel (launch overhead ~5us/launch dominates):
//   all blocks: zero out + warp-aggregated threshold compaction -> d_keys
//   last block (ticket): rank-by-count (no sort!), gather+write rows, tiny NMS
// x: (5, 80, 80) f32 channel-major. out: (6400, 5) f32.
// key = (~bits(score) << 32) | idx ; keys distinct =>
//   rank(k) = #{j : key_j < key_k} reproduces stable (score desc, idx asc).

#define NPIX 6400
#define NT   512
#define NBLK 16

__device__ unsigned long long d_keys[NPIX];
__device__ int d_cnt;     // zero-init; last block resets each run
__device__ int d_ticket;  // zero-init; last block resets each run

// dynamic smem (last block uses it; others just reserve):
//   [0,      65536)  u64 skeys[8192]
//   [65536, 167936)  float4 bx[6400]
//   [167936,193536)  int ndlist[6400]
//   [193536,199936)  u8 ndflag[6400]
//   [199936,206336)  u8 kb[6400]
#define SKEYS_OFF  0
#define BX_OFF     65536
#define NDLIST_OFF 167936
#define NDFLAG_OFF 193536
#define KB_OFF     199936
#define SMEM_BYTES 206336

__global__ void __launch_bounds__(NT, 1)
bb_all(const float* __restrict__ x, float* __restrict__ out) {
    extern __shared__ unsigned char smem[];
    unsigned long long* skeys  = (unsigned long long*)(smem + SKEYS_OFF);
    float4*             bx     = (float4*)(smem + BX_OFF);
    int*                ndlist = (int*)(smem + NDLIST_OFF);
    unsigned char*      ndflag = smem + NDFLAG_OFF;
    unsigned char*      kb     = smem + KB_OFF;
    __shared__ int s_last;

    const int tid  = threadIdx.x;
    const int lane = tid & 31;
    const int gtid = blockIdx.x * NT + tid;   // 0..8191

    // ---- phase A (all blocks): zero output + compact valid rows ----
    if (gtid < (NPIX * 5) / 4)                // 8000 float4
        ((float4*)out)[gtid] = make_float4(0.f, 0.f, 0.f, 0.f);

    {
        bool in_range = gtid < NPIX;
        float s = in_range ? x[gtid] : 0.f;   // channel 0 (prob)
        bool v = in_range && (s > 0.9f);
        unsigned bal = __ballot_sync(0xffffffffu, v);
        if (bal) {
            int leader = __ffs(bal) - 1;
            int base;
            if (lane == leader) base = atomicAdd(&d_cnt, __popc(bal));
            base = __shfl_sync(0xffffffffu, base, leader);
            if (v) {
                int p = base + __popc(bal & ((1u << lane) - 1u));
                d_keys[p] =
                    (((unsigned long long)(~__float_as_uint(s))) << 32) |
                    (unsigned)gtid;
            }
        }
    }

    // ---- ticket: last block to arrive does the serial tail ----
    __threadfence();
    __syncthreads();
    if (tid == 0)
        s_last = (atomicAdd(&d_ticket, 1) == NBLK - 1) ? 1 : 0;
    __syncthreads();
    if (!s_last) return;
    __threadfence();   // acquire: make other blocks' d_keys writes visible

    const int M = d_cnt;

    if (M > 0) {
        // ---- load keys to smem ----
        for (int k = tid; k < M; k += NT) skeys[k] = d_keys[k];
        __syncthreads();

        // ---- rank-by-count + gather + write rows ----
        // b5 = (f0, f1, f0+f2, f1+f3, f4); box = (f1, f0+f2, f1+f3, f4)
        for (int k = tid; k < M; k += NT) {
            unsigned long long key = skeys[k];
            int r = 0;
            int j = 0;
            for (; j + 4 <= M; j += 4) {
                r += (skeys[j]     < key);
                r += (skeys[j + 1] < key);
                r += (skeys[j + 2] < key);
                r += (skeys[j + 3] < key);
            }
            for (; j < M; j++) r += (skeys[j] < key);

            unsigned i = (unsigned)key;
            float f0 = __uint_as_float(~(unsigned)(key >> 32));
            float f1 = x[NPIX + i];
            float f2 = x[2 * NPIX + i];
            float f3 = x[3 * NPIX + i];
            float f4 = x[4 * NPIX + i];
            float c2 = f0 + f2;
            float c3 = f1 + f3;
            out[r * 5 + 0] = f0;
            out[r * 5 + 1] = f1;
            out[r * 5 + 2] = c2;
            out[r * 5 + 3] = c3;
            out[r * 5 + 4] = f4;
            bx[r] = make_float4(f1, c2, c3, f4);
            ndflag[r] = ((c3 - f1) > 0.f && (f4 - c2) > 0.f) ? 1 : 0;
        }
        __syncthreads();

        // ---- warp 0: greedy NMS over non-degenerate boxes only ----
        // degenerate boxes (w<=0 or h<=0) have IoU 0 with everything:
        // never suppressed, never suppress -> rows stay as written.
        if (tid < 32) {
            int g = 0;
            for (int base = 0; base < M; base += 32) {
                int r = base + lane;
                bool f = (r < M) && (ndflag[r] != 0);
                unsigned bal = __ballot_sync(0xffffffffu, f);
                if (f) ndlist[g + __popc(bal & ((1u << lane) - 1u))] = r;
                g += __popc(bal);
            }
            for (int i2 = 0; i2 < g; i2++) {
                int ri = ndlist[i2];
                float4 a = bx[ri];
                float aarea = fmaxf(a.z - a.x, 0.f) * fmaxf(a.w - a.y, 0.f);
                bool sup = false;
                for (int j = lane; j < i2; j += 32) {
                    if (kb[j]) {
                        float4 b = bx[ndlist[j]];
                        float barea = fmaxf(b.z - b.x, 0.f) *
                                      fmaxf(b.w - b.y, 0.f);
                        float iw = fminf(a.z, b.z) - fmaxf(a.x, b.x);
                        float ih = fminf(a.w, b.w) - fmaxf(a.y, b.y);
                        float inter = fmaxf(iw, 0.f) * fmaxf(ih, 0.f);
                        float uni = aarea + barea - inter;
                        if (inter / fmaxf(uni, 1e-9f) > 0.5f) sup = true;
                    }
                }
                sup = __any_sync(0xffffffffu, sup);
                if (lane == 0) {
                    kb[i2] = sup ? 0 : 1;
                    if (sup) {   // suppressed row -> zeros
                        out[ri * 5 + 0] = 0.f;
                        out[ri * 5 + 1] = 0.f;
                        out[ri * 5 + 2] = 0.f;
                        out[ri * 5 + 3] = 0.f;
                        out[ri * 5 + 4] = 0.f;
                    }
                }
                __syncwarp();
            }
        }
    }

    // ---- reset counters for next graph replay ----
    __syncthreads();
    if (tid == 0) { d_cnt = 0; d_ticket = 0; }
}

extern "C" void kernel_launch(void* const* d_in, const int* in_sizes, int n_in,
                              void* d_out, int out_size) {
    const float* x = (const float*)d_in[0];
    float* out = (float*)d_out;
    cudaFuncSetAttribute(bb_all,
                         cudaFuncAttributeMaxDynamicSharedMemorySize,
                         SMEM_BYTES);
    bb_all<<<NBLK, NT, SMEM_BYTES>>>(x, out);
}

// round 7
// speedup vs baseline: 1.7862x; 1.7862x over previous
#include <cuda_runtime.h>

// ReduceBoundingBoxes, SINGLE kernel, SINGLE block, bucketed counting sort.
// x: (5, 80, 80) f32 channel-major. out: (6400, 5) f32.
//
// key = (u64(~bits(score)) << 32) | idx ; ascending == (score desc, idx asc).
// Valid scores s in (0.9, 1.0) share exponent 126 -> u = ~bits(s) lies in
// (0xC0800000, 0xC099999A); bucket = clamp((u - 0xC0800000) >> 9, 0, 4095)
// is monotone in u. Expected bucket occupancy << 1, so in-bucket exact rank
// costs ~nothing; clamped/degenerate cases stay correct via full u64 compare.

#define NPIX 6400
#define NT   1024
#define NB   4096

// dynamic smem layout (bytes):
//   [0,     16384)  int cursor[4096]   (histogram, then running offsets)
//   [16384, 32896)  int base0[4097]    (exclusive bucket starts + total)
//   [32896, 84096)  u64 scat[6400]     (keys in bucket order)
//                   aliased as int ndlist[6400] after ranking is done
//   [84096, 186496) float4 bx[6400]    (boxes by rank)
//   [186496,192896) u8 ndflag[6400]
//   [192896,199296) u8 kb[6400]
#define CUR_OFF    0
#define BASE_OFF   16384
#define SCAT_OFF   32896
#define BX_OFF     84096
#define NDFLAG_OFF 186496
#define KB_OFF     192896
#define SMEM_BYTES 199296

__device__ __forceinline__ int bucket_of(unsigned u) {
    unsigned d = u - 0xC0800000u;
    int b = (u < 0xC0800000u) ? 0 : (int)(d >> 9);
    return b > (NB - 1) ? (NB - 1) : b;
}

__global__ void __launch_bounds__(NT, 1)
bb_kernel(const float* __restrict__ x, float* __restrict__ out) {
    extern __shared__ unsigned char smem[];
    int*                cursor = (int*)(smem + CUR_OFF);
    int*                base0  = (int*)(smem + BASE_OFF);
    unsigned long long* scat   = (unsigned long long*)(smem + SCAT_OFF);
    int*                ndlist = (int*)(smem + SCAT_OFF);   // alias, post-rank
    float4*             bx     = (float4*)(smem + BX_OFF);
    unsigned char*      ndflag = smem + NDFLAG_OFF;
    unsigned char*      kb     = smem + KB_OFF;
    __shared__ int wsum[32];
    __shared__ int sM;

    const int tid  = threadIdx.x;
    const int lane = tid & 31;
    const int wid  = tid >> 5;

    // ---- A: zero output (8000 float4) + zero histogram ----
    float4* o4 = (float4*)out;
    #pragma unroll
    for (int i = tid; i < (NPIX * 5) / 4; i += NT)
        o4[i] = make_float4(0.f, 0.f, 0.f, 0.f);
    #pragma unroll
    for (int i = tid; i < NB; i += NT) cursor[i] = 0;
    __syncthreads();

    // ---- B: histogram of valid scores ----
    #pragma unroll
    for (int i = tid; i < NPIX; i += NT) {
        float s = x[i];                       // channel 0 (prob)
        if (s > 0.9f)
            atomicAdd(&cursor[bucket_of(~__float_as_uint(s))], 1);
    }
    __syncthreads();

    // ---- C: exclusive prefix sum over 4096 buckets (4 per thread) ----
    const int t4 = tid * 4;
    int c0 = cursor[t4], c1 = cursor[t4 + 1];
    int c2 = cursor[t4 + 2], c3 = cursor[t4 + 3];
    int local = c0 + c1 + c2 + c3;
    int v = local;
    #pragma unroll
    for (int j = 1; j < 32; j <<= 1) {
        int n = __shfl_up_sync(0xffffffffu, v, j);
        if (lane >= j) v += n;
    }
    if (lane == 31) wsum[wid] = v;
    __syncthreads();
    if (wid == 0) {
        int w = wsum[lane];
        #pragma unroll
        for (int j = 1; j < 32; j <<= 1) {
            int n = __shfl_up_sync(0xffffffffu, w, j);
            if (lane >= j) w += n;
        }
        wsum[lane] = w;
        if (lane == 31) sM = w;               // total valid count
    }
    __syncthreads();
    int ex = v - local + (wid ? wsum[wid - 1] : 0);
    base0[t4]     = ex;
    base0[t4 + 1] = ex + c0;
    base0[t4 + 2] = ex + c0 + c1;
    base0[t4 + 3] = ex + c0 + c1 + c2;
    cursor[t4]     = ex;
    cursor[t4 + 1] = ex + c0;
    cursor[t4 + 2] = ex + c0 + c1;
    cursor[t4 + 3] = ex + c0 + c1 + c2;
    if (tid == 0) base0[NB] = sM;
    __syncthreads();
    const int M = sM;

    if (M > 0) {
        // ---- D: scatter keys into bucket order (x is L1-hot now) ----
        #pragma unroll
        for (int i = tid; i < NPIX; i += NT) {
            float s = x[i];
            if (s > 0.9f) {
                unsigned u = ~__float_as_uint(s);
                int slot = atomicAdd(&cursor[bucket_of(u)], 1);
                scat[slot] = (((unsigned long long)u) << 32) | (unsigned)i;
            }
        }
        __syncthreads();

        // ---- E: exact rank (in-bucket compares; usually none) + gather ----
        // b5 = (f0, f1, f0+f2, f1+f3, f4); box = (f1, f0+f2, f1+f3, f4)
        for (int p = tid; p < M; p += NT) {
            unsigned long long key = scat[p];
            unsigned u = (unsigned)(key >> 32);
            int b = bucket_of(u);
            int s0 = base0[b], e0 = base0[b + 1];
            int r = s0;
            if (e0 - s0 > 1)
                for (int q = s0; q < e0; q++) r += (scat[q] < key);

            unsigned i = (unsigned)key;
            float f0 = __uint_as_float(~u);
            float f1 = x[NPIX + i];
            float f2 = x[2 * NPIX + i];
            float f3 = x[3 * NPIX + i];
            float f4 = x[4 * NPIX + i];
            float cc2 = f0 + f2;
            float cc3 = f1 + f3;
            out[r * 5 + 0] = f0;
            out[r * 5 + 1] = f1;
            out[r * 5 + 2] = cc2;
            out[r * 5 + 3] = cc3;
            out[r * 5 + 4] = f4;
            bx[r] = make_float4(f1, cc2, cc3, f4);
            ndflag[r] = ((cc3 - f1) > 0.f && (f4 - cc2) > 0.f) ? 1 : 0;
        }
        __syncthreads();   // scat dead after this point -> ndlist alias OK

        // ---- F: warp 0 — greedy NMS over non-degenerate boxes only ----
        // degenerate boxes (w<=0 or h<=0) have IoU 0 with everything:
        // never suppressed, never suppress -> rows stay as written.
        if (tid < 32) {
            int g = 0;
            for (int base = 0; base < M; base += 32) {
                int r = base + lane;
                bool f = (r < M) && (ndflag[r] != 0);
                unsigned bal = __ballot_sync(0xffffffffu, f);
                if (f) ndlist[g + __popc(bal & ((1u << lane) - 1u))] = r;
                g += __popc(bal);
            }
            for (int i2 = 0; i2 < g; i2++) {
                int ri = ndlist[i2];
                float4 a = bx[ri];
                float aarea = fmaxf(a.z - a.x, 0.f) * fmaxf(a.w - a.y, 0.f);
                bool sup = false;
                for (int j = lane; j < i2; j += 32) {
                    if (kb[j]) {
                        float4 b2 = bx[ndlist[j]];
                        float barea = fmaxf(b2.z - b2.x, 0.f) *
                                      fmaxf(b2.w - b2.y, 0.f);
                        float iw = fminf(a.z, b2.z) - fmaxf(a.x, b2.x);
                        float ih = fminf(a.w, b2.w) - fmaxf(a.y, b2.y);
                        float inter = fmaxf(iw, 0.f) * fmaxf(ih, 0.f);
                        float uni = aarea + barea - inter;
                        if (inter / fmaxf(uni, 1e-9f) > 0.5f) sup = true;
                    }
                }
                sup = __any_sync(0xffffffffu, sup);
                if (lane == 0) {
                    kb[i2] = sup ? 0 : 1;
                    if (sup) {   // suppressed row -> zeros
                        out[ri * 5 + 0] = 0.f;
                        out[ri * 5 + 1] = 0.f;
                        out[ri * 5 + 2] = 0.f;
                        out[ri * 5 + 3] = 0.f;
                        out[ri * 5 + 4] = 0.f;
                    }
                }
                __syncwarp();
            }
        }
    }
}

extern "C" void kernel_launch(void* const* d_in, const int* in_sizes, int n_in,
                              void* d_out, int out_size) {
    const float* x = (const float*)d_in[0];
    float* out = (float*)d_out;
    cudaFuncSetAttribute(bb_kernel,
                         cudaFuncAttributeMaxDynamicSharedMemorySize,
                         SMEM_BYTES);
    bb_kernel<<<1, NT, SMEM_BYTES>>>(x, out);
}

// round 8
// speedup vs baseline: 1.8221x; 1.0201x over previous
#include <cuda_runtime.h>

// ReduceBoundingBoxes, SINGLE kernel, SINGLE block, bucketed counting sort,
// register-resident keys, L2 prefetch for gather, smem row staging with one
// coalesced output sweep.
// x: (5, 80, 80) f32 channel-major. out: (6400, 5) f32.
//
// key = (u64(~bits(score)) << 32) | idx ; ascending == (score desc, idx asc).
// Valid scores s in (0.9, 1.0) share exponent 126 -> u = ~bits(s) lies in
// (0xC0800000, 0xC099999A); bucket = clamp((u - 0xC0800000) >> 9, 0, 4095)
// is monotone in u. Out-of-range scores clamp into end buckets and are
// resolved by exact in-bucket u64 compares -> correct for any input.

#define NPIX 6400
#define NT   1024
#define NB   4096
#define NIT  7          // ceil(6400 / 1024)

// dynamic smem layout (bytes):
//   [0,     16384)  int cursor[4096]  (hist -> running offsets)
//                   reused after scatter: u8 ndflag[6400] @0, u8 kb[6400] @6400
//   [16384, 32896)  int base0[4097]   (exclusive bucket starts + total)
//   [32896, 84096)  u64 scat[6400]    (keys in bucket order)
//                   aliased as int ndlist[6400] after ranking
//   [84096, 212096) float stage[32000] (b5 rows by rank)
#define CUR_OFF    0
#define BASE_OFF   16384
#define SCAT_OFF   32896
#define STAGE_OFF  84096
#define SMEM_BYTES 212096

__device__ __forceinline__ int bucket_of(unsigned u) {
    unsigned d = u - 0xC0800000u;
    int b = (u < 0xC0800000u) ? 0 : (int)(d >> 9);
    return b > (NB - 1) ? (NB - 1) : b;
}

__global__ void __launch_bounds__(NT, 1)
bb_kernel(const float* __restrict__ x, float* __restrict__ out) {
    extern __shared__ unsigned char smem[];
    int*                cursor = (int*)(smem + CUR_OFF);
    unsigned char*      ndflag = smem + CUR_OFF;          // reuse post-scatter
    unsigned char*      kb     = smem + CUR_OFF + 6400;   // reuse post-scatter
    int*                base0  = (int*)(smem + BASE_OFF);
    unsigned long long* scat   = (unsigned long long*)(smem + SCAT_OFF);
    int*                ndlist = (int*)(smem + SCAT_OFF); // alias, post-rank
    float*              stage  = (float*)(smem + STAGE_OFF);
    __shared__ int wsum[32];
    __shared__ int sM;

    const int tid  = threadIdx.x;
    const int lane = tid & 31;
    const int wid  = tid >> 5;

    // ---- A: zero histogram, prefetch ch1..4 to L2, load ch0 into regs ----
    #pragma unroll
    for (int i = tid; i < NB; i += NT) cursor[i] = 0;
    if (tid < 800) {   // 102400 B / 128 B lines
        const char* p = (const char*)(x + NPIX) + tid * 128;
        asm volatile("prefetch.global.L2 [%0];" :: "l"(p));
    }
    unsigned ru[NIT];
    int vmask = 0;
    #pragma unroll
    for (int it = 0; it < NIT; it++) {
        int i = tid + it * NT;
        if (i < NPIX) {
            float s = x[i];              // channel 0 (prob)
            if (s > 0.9f) { ru[it] = ~__float_as_uint(s); vmask |= 1 << it; }
        }
    }
    __syncthreads();

    // ---- B: histogram from registers ----
    #pragma unroll
    for (int it = 0; it < NIT; it++)
        if (vmask & (1 << it))
            atomicAdd(&cursor[bucket_of(ru[it])], 1);
    __syncthreads();

    // ---- C: exclusive prefix sum over 4096 buckets (4 per thread) ----
    const int t4 = tid * 4;
    int c0 = cursor[t4], c1 = cursor[t4 + 1];
    int c2 = cursor[t4 + 2], c3 = cursor[t4 + 3];
    int local = c0 + c1 + c2 + c3;
    int v = local;
    #pragma unroll
    for (int j = 1; j < 32; j <<= 1) {
        int n = __shfl_up_sync(0xffffffffu, v, j);
        if (lane >= j) v += n;
    }
    if (lane == 31) wsum[wid] = v;
    __syncthreads();
    if (wid == 0) {
        int w = wsum[lane];
        #pragma unroll
        for (int j = 1; j < 32; j <<= 1) {
            int n = __shfl_up_sync(0xffffffffu, w, j);
            if (lane >= j) w += n;
        }
        wsum[lane] = w;
        if (lane == 31) sM = w;          // total valid count
    }
    __syncthreads();
    int ex = v - local + (wid ? wsum[wid - 1] : 0);
    base0[t4]     = ex;
    base0[t4 + 1] = ex + c0;
    base0[t4 + 2] = ex + c0 + c1;
    base0[t4 + 3] = ex + c0 + c1 + c2;
    cursor[t4]     = ex;
    cursor[t4 + 1] = ex + c0;
    cursor[t4 + 2] = ex + c0 + c1;
    cursor[t4 + 3] = ex + c0 + c1 + c2;
    if (tid == 0) base0[NB] = sM;
    __syncthreads();
    const int M = sM;

    // ---- D: scatter keys from registers + zero output tail [M*5,32000) ----
    #pragma unroll
    for (int it = 0; it < NIT; it++) {
        if (vmask & (1 << it)) {
            unsigned u = ru[it];
            int slot = atomicAdd(&cursor[bucket_of(u)], 1);
            scat[slot] = (((unsigned long long)u) << 32) |
                         (unsigned)(tid + it * NT);
        }
    }
    {
        int start = M * 5;
        int a0 = (start + 3) & ~3;
        if (a0 > NPIX * 5) a0 = NPIX * 5;
        if (tid < a0 - start) out[start + tid] = 0.f;       // <=3 scalars
        float4* o4 = (float4*)out;
        for (int i = (a0 >> 2) + tid; i < (NPIX * 5) / 4; i += NT)
            o4[i] = make_float4(0.f, 0.f, 0.f, 0.f);
    }
    __syncthreads();   // cursor dead after this -> ndflag/kb reuse OK

    if (M > 0) {
        // ---- E: exact rank + gather ch1..4 (L2-warm) -> smem stage ----
        // b5 = (f0, f1, f0+f2, f1+f3, f4); box = (f1, f0+f2, f1+f3, f4)
        for (int p = tid; p < M; p += NT) {
            unsigned long long key = scat[p];
            unsigned u = (unsigned)(key >> 32);
            int b = bucket_of(u);
            int s0 = base0[b], e0 = base0[b + 1];
            int r = s0;
            if (e0 - s0 > 1)
                for (int q = s0; q < e0; q++) r += (scat[q] < key);

            unsigned i = (unsigned)key;
            float f0 = __uint_as_float(~u);
            float f1 = x[NPIX + i];
            float f2 = x[2 * NPIX + i];
            float f3 = x[3 * NPIX + i];
            float f4 = x[4 * NPIX + i];
            float cc2 = f0 + f2;
            float cc3 = f1 + f3;
            stage[r * 5 + 0] = f0;
            stage[r * 5 + 1] = f1;
            stage[r * 5 + 2] = cc2;
            stage[r * 5 + 3] = cc3;
            stage[r * 5 + 4] = f4;
            ndflag[r] = ((cc3 - f1) > 0.f && (f4 - cc2) > 0.f) ? 1 : 0;
        }
        __syncthreads();   // scat dead -> ndlist alias OK

        // ---- F: warp 0 — greedy NMS over non-degenerate boxes only ----
        // degenerate boxes (w<=0 or h<=0) have IoU 0 with everything:
        // never suppressed, never suppress -> rows stay as staged.
        if (tid < 32) {
            int g = 0;
            for (int base = 0; base < M; base += 32) {
                int r = base + lane;
                bool f = (r < M) && (ndflag[r] != 0);
                unsigned bal = __ballot_sync(0xffffffffu, f);
                if (f) ndlist[g + __popc(bal & ((1u << lane) - 1u))] = r;
                g += __popc(bal);
            }
            for (int i2 = 0; i2 < g; i2++) {
                int ri = ndlist[i2];
                float ax0 = stage[ri * 5 + 1], ay0 = stage[ri * 5 + 2];
                float ax1 = stage[ri * 5 + 3], ay1 = stage[ri * 5 + 4];
                float aarea = fmaxf(ax1 - ax0, 0.f) * fmaxf(ay1 - ay0, 0.f);
                bool sup = false;
                for (int j = lane; j < i2; j += 32) {
                    if (kb[j]) {
                        int rj = ndlist[j];
                        float bx0 = stage[rj * 5 + 1], by0 = stage[rj * 5 + 2];
                        float bx1 = stage[rj * 5 + 3], by1 = stage[rj * 5 + 4];
                        float barea = fmaxf(bx1 - bx0, 0.f) *
                                      fmaxf(by1 - by0, 0.f);
                        float iw = fminf(ax1, bx1) - fmaxf(ax0, bx0);
                        float ih = fminf(ay1, by1) - fmaxf(ay0, by0);
                        float inter = fmaxf(iw, 0.f) * fmaxf(ih, 0.f);
                        float uni = aarea + barea - inter;
                        if (inter / fmaxf(uni, 1e-9f) > 0.5f) sup = true;
                    }
                }
                sup = __any_sync(0xffffffffu, sup);
                if (lane == 0) {
                    kb[i2] = sup ? 0 : 1;
                    if (sup) {   // suppressed -> zero staged row
                        stage[ri * 5 + 0] = 0.f;
                        stage[ri * 5 + 1] = 0.f;
                        stage[ri * 5 + 2] = 0.f;
                        stage[ri * 5 + 3] = 0.f;
                        stage[ri * 5 + 4] = 0.f;
                    }
                }
                __syncwarp();
            }
        }
        __syncthreads();

        // ---- G: coalesced write out[0, M*5) from stage ----
        {
            int total = M * 5;
            int nf4 = total >> 2;
            const float4* s4 = (const float4*)stage;
            float4* o4 = (float4*)out;
            for (int i = tid; i < nf4; i += NT) o4[i] = s4[i];
            int rem = total & 3;
            if (tid < rem) out[nf4 * 4 + tid] = stage[nf4 * 4 + tid];
        }
    }
}

extern "C" void kernel_launch(void* const* d_in, const int* in_sizes, int n_in,
                              void* d_out, int out_size) {
    const float* x = (const float*)d_in[0];
    float* out = (float*)d_out;
    cudaFuncSetAttribute(bb_kernel,
                         cudaFuncAttributeMaxDynamicSharedMemorySize,
                         SMEM_BYTES);
    bb_kernel<<<1, NT, SMEM_BYTES>>>(x, out);
}